// round 8
// baseline (speedup 1.0000x reference)
#include <cuda_runtime.h>

#define BSZ 32
#define NA  8400
#define NM  100
#define NC  80
#define TK  13
#define EPSF 1e-9f

// ---------------- scratch (__device__ globals; no allocation) ----------------
__device__ int   g_cnt[BSZ * NA];    // #gts claiming this anchor via topk
__device__ int   g_claim[BSZ * NA];  // claiming gt j (valid when cnt==1)
__device__ int   g_jm[BSZ * NA];     // final assigned gt (-1 = negative anchor)
__device__ float g_m[BSZ * NA];      // align metric at (jm, i)
__device__ int   g_pa[BSZ * NM];     // pos_align  (float bits, atomicMax)
__device__ int   g_po[BSZ * NM];     // pos_overlaps (float bits, atomicMax)
__device__ int   g_cls[BSZ * NA];    // assigned class (-1 if negative)
__device__ float g_norm[BSZ * NA];   // score normalizer

__device__ __forceinline__ float iou_f(float4 g, float4 p, float areaG, float areaP) {
    float lx = fmaxf(g.x, p.x), ly = fmaxf(g.y, p.y);
    float rx = fminf(g.z, p.z), ry = fminf(g.w, p.w);
    float w = fmaxf(rx - lx, 0.f), h = fmaxf(ry - ly, 0.f);
    float inter = w * h;
    return inter / ((areaG + areaP) - inter + EPSF);   // same assoc as reference
}

// ---------------- K0: init counters ----------------
__global__ void k_init() {
    int t = blockIdx.x * blockDim.x + threadIdx.x;
    if (t < BSZ * NA) g_cnt[t] = 0;
    if (t < BSZ * NM) { g_pa[t] = 0; g_po[t] = 0; }
}

// ---------------- K1: per-(b,j) top-13 + claims ----------------
// key = (float_bits(metric) << 32) | ~i  -> max-order == (metric desc, index asc),
// exactly lax.top_k's tie-break. metric >= 0 so float bits are monotonic.
__global__ __launch_bounds__(256) void k_topk(
    const float* __restrict__ ps, const float* __restrict__ pb,
    const float* __restrict__ ap, const int* __restrict__ gl,
    const float* __restrict__ gb, const float* __restrict__ mg)
{
    int j = blockIdx.x, b = blockIdx.y;
    float4 g = ((const float4*)gb)[b * NM + j];
    int   lab = gl[b * NM + j];
    float msk = mg[b * NM + j];
    float areaG = (g.z - g.x) * (g.w - g.y);
    const float*  psb = ps + ((size_t)b * NA) * NC + lab;
    const float4* pbb = ((const float4*)pb) + (size_t)b * NA;
    const float2* ap2 = (const float2*)ap;

    unsigned long long loc[TK];
#pragma unroll
    for (int k = 0; k < TK; k++) loc[k] = 0ull;

    for (int i = threadIdx.x; i < NA; i += 256) {
        float2 a = ap2[i];
        float d = fminf(fminf(a.x - g.x, a.y - g.y), fminf(g.z - a.x, g.w - a.y));
        float metric = 0.f;
        if (d > EPSF) {   // is_in_gts gate: skip IoU + score gather for ~99% of items
            float4 p = pbb[i];
            float areaP = (p.z - p.x) * (p.w - p.y);
            float iou = iou_f(g, p, areaG, areaP);
            float s = __ldg(&psb[(size_t)i * NC]);
            float i2 = iou * iou;
            metric = s * (i2 * i2 * i2);
        }
        unsigned long long key =
            ((unsigned long long)__float_as_uint(metric) << 32) | (unsigned)(~(unsigned)i);
        if (key > loc[TK - 1]) {
            loc[TK - 1] = key;
#pragma unroll
            for (int k = TK - 1; k > 0; k--) {
                unsigned long long lo = loc[k], hi = loc[k - 1];
                if (lo > hi) { loc[k - 1] = lo; loc[k] = hi; }
            }
        }
    }

    // block merge: 13 rounds of argmax over 256 thread-list heads
    __shared__ unsigned long long sK[256];
    __shared__ int sI[256];
    __shared__ unsigned long long win[TK];
    int p = 0;
    for (int r = 0; r < TK; r++) {
        sK[threadIdx.x] = (p < TK) ? loc[p] : 0ull;
        sI[threadIdx.x] = threadIdx.x;
        __syncthreads();
        for (int s = 128; s > 0; s >>= 1) {
            if (threadIdx.x < s) {
                if (sK[threadIdx.x + s] > sK[threadIdx.x]) {
                    sK[threadIdx.x] = sK[threadIdx.x + s];
                    sI[threadIdx.x] = sI[threadIdx.x + s];
                }
            }
            __syncthreads();
        }
        if (threadIdx.x == 0) win[r] = sK[0];
        int w = sI[0];
        __syncthreads();
        if (threadIdx.x == w) p++;
    }

    // claims: only positive-metric winners matter (zero-metric topk entries are
    // annihilated by is_in_gts in mask_pos); masked gt rows claim nothing.
    if (threadIdx.x < TK && msk > 0.f) {
        unsigned long long kk = win[threadIdx.x];
        float v = __uint_as_float((unsigned)(kk >> 32));
        if (v > 0.f) {
            int idx = (int)(~(unsigned)(kk & 0xFFFFFFFFull));
            atomicAdd(&g_cnt[b * NA + idx], 1);
            g_claim[b * NA + idx] = j;   // unique writer when cnt==1 (only case read)
        }
    }
}

// ---------------- K2: resolve assignment per anchor ----------------
__global__ __launch_bounds__(128) void k_assign(
    const float* __restrict__ ps, const float* __restrict__ pb,
    const float* __restrict__ gb, const int* __restrict__ gl)
{
    int b = blockIdx.y;
    __shared__ float4 sG[NM];
    __shared__ int    sL[NM];
    for (int t = threadIdx.x; t < NM; t += 128) {
        sG[t] = ((const float4*)gb)[b * NM + t];
        sL[t] = gl[b * NM + t];
    }
    __syncthreads();
    int i = blockIdx.x * 128 + threadIdx.x;
    if (i >= NA) return;
    int o = b * NA + i;
    int c = g_cnt[o];
    int jm = -1;
    float mval = 0.f;
    if (c > 0) {
        float4 p = ((const float4*)pb)[(size_t)b * NA + i];
        float areaP = (p.z - p.x) * (p.w - p.y);
        if (c == 1) {
            jm = g_claim[o];
        } else {
            // multi-claimed anchor -> argmax_j overlaps over ALL 100 gts (first-max)
            float best = -1.f;
            for (int jj = 0; jj < NM; jj++) {
                float4 gg = sG[jj];
                float areaG = (gg.z - gg.x) * (gg.w - gg.y);
                float iou = iou_f(gg, p, areaG, areaP);
                if (iou > best) { best = iou; jm = jj; }
            }
        }
        float4 gg = sG[jm];
        float areaG = (gg.z - gg.x) * (gg.w - gg.y);
        float iou = iou_f(gg, p, areaG, areaP);
        float s = ps[(size_t)o * NC + sL[jm]];
        float i2 = iou * iou;
        mval = s * (i2 * i2 * i2);
        atomicMax(&g_pa[b * NM + jm], __float_as_int(mval));  // nonneg floats: int order ok
        atomicMax(&g_po[b * NM + jm], __float_as_int(iou));
    }
    g_jm[o] = jm;
    g_m[o]  = mval;
}

// ---------------- K3: finalize labels / bboxes / pos + (cls,norm) ----------------
__global__ __launch_bounds__(128) void k_final(
    const float* __restrict__ gb, const int* __restrict__ gl,
    float* __restrict__ oL, float* __restrict__ oB, float* __restrict__ oP)
{
    int b = blockIdx.y;
    int i = blockIdx.x * 128 + threadIdx.x;
    if (i >= NA) return;
    int o = b * NA + i;
    int jm = g_jm[o];
    bool pos = (jm >= 0);
    int ag = pos ? jm : 0;              // argmax of all-zero column = 0
    int lab = gl[b * NM + ag];
    if (lab < 0) lab = 0;
    float nrm = 0.f;
    if (pos) {
        float pa = __int_as_float(g_pa[b * NM + jm]);
        float po = __int_as_float(g_po[b * NM + jm]);
        nrm = g_m[o] * po / (pa + EPSF);
    }
    if (oL) oL[o] = pos ? (float)lab : (float)NC;
    if (oB) ((float4*)oB)[o] = ((const float4*)gb)[b * NM + ag];  // unmasked by pos (matches ref)
    if (oP) oP[o] = pos ? 1.f : 0.f;
    g_cls[o]  = pos ? lab : -1;
    g_norm[o] = nrm;
}

// ---------------- K4: coalesced scores (one-hot * norm), float4 ----------------
__global__ __launch_bounds__(256) void k_scores(float* __restrict__ oS)
{
    const int T4 = BSZ * NA * NC / 4;   // 5,376,000
    int e = blockIdx.x * 256 + threadIdx.x;
    if (e >= T4) return;
    int a  = e / 20;              // anchor (b*NA+i); 80 floats = 20 float4, no straddle
    int c0 = (e - a * 20) * 4;
    int cls = g_cls[a];
    float nv = g_norm[a];
    float4 v = make_float4(0.f, 0.f, 0.f, 0.f);
    int d = cls - c0;
    if (d >= 0 && d < 4) {
        if      (d == 0) v.x = nv;
        else if (d == 1) v.y = nv;
        else if (d == 2) v.z = nv;
        else             v.w = nv;
    }
    ((float4*)oS)[e] = v;
}

// ---------------- launch ----------------
extern "C" void kernel_launch(void* const* d_in, const int* in_sizes, int n_in,
                              void* d_out, int out_size)
{
    const float* ps = (const float*)d_in[0];   // pred_scores  (32,8400,80)
    const float* pb = (const float*)d_in[1];   // pred_bboxes  (32,8400,4)
    const float* ap = (const float*)d_in[2];   // anchor_points(8400,2)
    const int*   gl = (const int*)  d_in[3];   // gt_labels    (32,100,1)
    const float* gb = (const float*)d_in[4];   // gt_bboxes    (32,100,4)
    const float* mg = (const float*)d_in[5];   // mask_gt      (32,100,1)

    float* out = (float*)d_out;
    float *oL = nullptr, *oB = nullptr, *oS = nullptr, *oP = nullptr;
    const int FULL = BSZ * NA * (1 + 4 + NC + 1);   // 23,116,800
    if (out_size == FULL) {
        oL = out;
        oB = out + BSZ * NA;
        oS = oB + BSZ * NA * 4;
        oP = oS + (size_t)BSZ * NA * NC;
    } else {
        // fallback: assume scores-only output
        oS = out;
    }

    k_init<<<(BSZ * NA + 255) / 256, 256>>>();
    k_topk<<<dim3(NM, BSZ), 256>>>(ps, pb, ap, gl, gb, mg);
    k_assign<<<dim3((NA + 127) / 128, BSZ), 128>>>(ps, pb, gb, gl);
    k_final<<<dim3((NA + 127) / 128, BSZ), 128>>>(gb, gl, oL, oB, oP);
    k_scores<<<(BSZ * NA * NC / 4 + 255) / 256, 256>>>(oS);
}

// round 9
// speedup vs baseline: 1.1267x; 1.1267x over previous
#include <cuda_runtime.h>

#define BSZ 32
#define NA  8400
#define NM  100
#define NC  80
#define TK  13
#define EPSF 1e-9f

// ---------------- scratch (__device__ globals; no allocation) ----------------
__device__ int   g_cnt[BSZ * NA];    // #gts claiming this anchor via topk
__device__ int   g_claim[BSZ * NA];  // claiming gt j (valid when cnt==1)
__device__ int   g_jm[BSZ * NA];     // final assigned gt (-1 = negative anchor)
__device__ float g_m[BSZ * NA];      // align metric at (jm, i)
__device__ int   g_pa[BSZ * NM];     // pos_align  (float bits, atomicMax)
__device__ int   g_po[BSZ * NM];     // pos_overlaps (float bits, atomicMax)

__device__ __forceinline__ float iou_f(float4 g, float4 p, float areaG, float areaP) {
    float lx = fmaxf(g.x, p.x), ly = fmaxf(g.y, p.y);
    float rx = fminf(g.z, p.z), ry = fminf(g.w, p.w);
    float w = fmaxf(rx - lx, 0.f), h = fmaxf(ry - ly, 0.f);
    float inter = w * h;
    return inter / ((areaG + areaP) - inter + EPSF);   // same assoc as reference
}

// ---------------- K0: init counters ----------------
__global__ void k_init() {
    int t = blockIdx.x * blockDim.x + threadIdx.x;
    if (t < BSZ * NA) g_cnt[t] = 0;
    if (t < BSZ * NM) { g_pa[t] = 0; g_po[t] = 0; }
}

// ---------------- K1: one WARP per (b,j): top-13 + claims, no barriers ----------
// key = (float_bits(metric) << 32) | ~i  -> max-order == (metric desc, index asc),
// exactly lax.top_k's tie-break. metric >= 0 so float bits are monotonic.
// Only metric>0 keys are kept: top-13 winners with metric==0 are annihilated by
// is_in_gts in mask_pos, so the positive subset of top-13(all) == top-13(positives).
__global__ __launch_bounds__(256) void k_topk(
    const float* __restrict__ ps, const float* __restrict__ pb,
    const float* __restrict__ ap, const int* __restrict__ gl,
    const float* __restrict__ gb, const float* __restrict__ mg)
{
    const unsigned FULL = 0xFFFFFFFFu;
    int wid  = blockIdx.x * 8 + (threadIdx.x >> 5);   // global warp id = b*NM + j
    int lane = threadIdx.x & 31;
    if (wid >= BSZ * NM) return;
    int b = wid / NM, j = wid - b * NM;

    if (mg[b * NM + j] <= 0.f) return;   // masked gt claims nothing (counts=13>1 -> zeroed)

    float4 g = ((const float4*)gb)[b * NM + j];
    int   lab = gl[b * NM + j];
    float areaG = (g.z - g.x) * (g.w - g.y);
    const float*  psb = ps + ((size_t)b * NA) * NC + lab;
    const float4* pbb = ((const float4*)pb) + (size_t)b * NA;
    const float2* ap2 = (const float2*)ap;

    unsigned long long loc[TK];
#pragma unroll
    for (int k = 0; k < TK; k++) loc[k] = 0ull;

    for (int i = lane; i < NA; i += 32) {
        float2 a = ap2[i];
        float d = fminf(fminf(a.x - g.x, a.y - g.y), fminf(g.z - a.x, g.w - a.y));
        if (d > EPSF) {   // is_in_gts gate (~1% pass): only then IoU + score gather
            float4 p = pbb[i];
            float areaP = (p.z - p.x) * (p.w - p.y);
            float iou = iou_f(g, p, areaG, areaP);
            float s = __ldg(&psb[(size_t)i * NC]);
            float i2 = iou * iou;
            float metric = s * (i2 * i2 * i2);
            if (metric > 0.f) {
                unsigned long long key =
                    ((unsigned long long)__float_as_uint(metric) << 32) | (unsigned)(~(unsigned)i);
                if (key > loc[TK - 1]) {
                    loc[TK - 1] = key;
#pragma unroll
                    for (int k = TK - 1; k > 0; k--) {
                        unsigned long long lo = loc[k], hi = loc[k - 1];
                        if (lo > hi) { loc[k - 1] = lo; loc[k] = hi; }
                    }
                }
            }
        }
    }

    // warp merge: up to 13 rounds of warp-argmax over per-lane sorted heads.
    // Keys are unique (embed ~i) -> exactly one winner lane per round.
#pragma unroll 1
    for (int r = 0; r < TK; r++) {
        unsigned long long best = loc[0];
#pragma unroll
        for (int off = 16; off; off >>= 1) {
            unsigned long long o = __shfl_xor_sync(FULL, best, off);
            if (o > best) best = o;
        }
        if (best == 0ull) break;          // no positive candidates left
        unsigned ball = __ballot_sync(FULL, loc[0] == best);
        if (lane == __ffs(ball) - 1) {
            int idx = (int)(~(unsigned)(best & 0xFFFFFFFFull));
            atomicAdd(&g_cnt[b * NA + idx], 1);
            g_claim[b * NA + idx] = j;    // unique writer when cnt==1 (only case read)
#pragma unroll
            for (int k = 0; k < TK - 1; k++) loc[k] = loc[k + 1];
            loc[TK - 1] = 0ull;
        }
    }
}

// ---------------- K2: resolve assignment per anchor ----------------
__global__ __launch_bounds__(128) void k_assign(
    const float* __restrict__ ps, const float* __restrict__ pb,
    const float* __restrict__ gb, const int* __restrict__ gl)
{
    int b = blockIdx.y;
    __shared__ float4 sG[NM];
    __shared__ int    sL[NM];
    for (int t = threadIdx.x; t < NM; t += 128) {
        sG[t] = ((const float4*)gb)[b * NM + t];
        sL[t] = gl[b * NM + t];
    }
    __syncthreads();
    int i = blockIdx.x * 128 + threadIdx.x;
    if (i >= NA) return;
    int o = b * NA + i;
    int c = g_cnt[o];
    int jm = -1;
    float mval = 0.f;
    if (c > 0) {
        float4 p = ((const float4*)pb)[(size_t)b * NA + i];
        float areaP = (p.z - p.x) * (p.w - p.y);
        if (c == 1) {
            jm = g_claim[o];
        } else {
            // multi-claimed anchor -> argmax_j overlaps over ALL 100 gts (first-max)
            float best = -1.f;
            for (int jj = 0; jj < NM; jj++) {
                float4 gg = sG[jj];
                float areaG = (gg.z - gg.x) * (gg.w - gg.y);
                float iou = iou_f(gg, p, areaG, areaP);
                if (iou > best) { best = iou; jm = jj; }
            }
        }
        float4 gg = sG[jm];
        float areaG = (gg.z - gg.x) * (gg.w - gg.y);
        float iou = iou_f(gg, p, areaG, areaP);
        float s = ps[(size_t)o * NC + sL[jm]];
        float i2 = iou * iou;
        mval = s * (i2 * i2 * i2);
        atomicMax(&g_pa[b * NM + jm], __float_as_int(mval));  // nonneg floats: int order ok
        atomicMax(&g_po[b * NM + jm], __float_as_int(iou));
    }
    g_jm[o] = jm;
    g_m[o]  = mval;
}

// ---------------- K3: fused finalize + coalesced scores ----------------
// Block = 256 threads handles 64 anchors of one batch. Threads 0..63 compute the
// per-anchor outputs (labels/bboxes/pos) and stage (cls, norm) in smem; then all
// 256 threads stream the 64*80-float score tile as coalesced float4 stores.
__global__ __launch_bounds__(256) void k_final(
    const float* __restrict__ gb, const int* __restrict__ gl,
    float* __restrict__ oL, float* __restrict__ oB,
    float* __restrict__ oS, float* __restrict__ oP)
{
    __shared__ int   sCls[64];
    __shared__ float sNrm[64];
    int b  = blockIdx.y;
    int a0 = blockIdx.x * 64;

    if (threadIdx.x < 64) {
        int i = a0 + threadIdx.x;
        if (i < NA) {
            int o = b * NA + i;
            int jm = g_jm[o];
            bool pos = (jm >= 0);
            int ag = pos ? jm : 0;            // argmax of all-zero column = 0
            int lab = gl[b * NM + ag];
            if (lab < 0) lab = 0;
            float nrm = 0.f;
            if (pos) {
                float pa = __int_as_float(g_pa[b * NM + jm]);
                float po = __int_as_float(g_po[b * NM + jm]);
                nrm = g_m[o] * po / (pa + EPSF);
            }
            if (oL) oL[o] = pos ? (float)lab : (float)NC;
            if (oB) ((float4*)oB)[o] = ((const float4*)gb)[b * NM + ag]; // unmasked (matches ref)
            if (oP) oP[o] = pos ? 1.f : 0.f;
            sCls[threadIdx.x] = pos ? lab : -1;
            sNrm[threadIdx.x] = nrm;
        }
    }
    __syncthreads();

    // 64 anchors * 20 float4 = 1280 stores; 5 per thread, coalesced
    float4* dst = ((float4*)oS) + ((size_t)b * NA + a0) * 20;
#pragma unroll
    for (int t = threadIdx.x; t < 64 * 20; t += 256) {
        int al = t / 20;
        if (a0 + al >= NA) break;
        int c0 = (t - al * 20) * 4;
        int cls = sCls[al];
        float nv = sNrm[al];
        float4 v = make_float4(0.f, 0.f, 0.f, 0.f);
        int d = cls - c0;
        if (d >= 0 && d < 4) {
            if      (d == 0) v.x = nv;
            else if (d == 1) v.y = nv;
            else if (d == 2) v.z = nv;
            else             v.w = nv;
        }
        dst[t] = v;
    }
}

// ---------------- launch ----------------
extern "C" void kernel_launch(void* const* d_in, const int* in_sizes, int n_in,
                              void* d_out, int out_size)
{
    const float* ps = (const float*)d_in[0];   // pred_scores  (32,8400,80)
    const float* pb = (const float*)d_in[1];   // pred_bboxes  (32,8400,4)
    const float* ap = (const float*)d_in[2];   // anchor_points(8400,2)
    const int*   gl = (const int*)  d_in[3];   // gt_labels    (32,100,1)
    const float* gb = (const float*)d_in[4];   // gt_bboxes    (32,100,4)
    const float* mg = (const float*)d_in[5];   // mask_gt      (32,100,1)

    float* out = (float*)d_out;
    float *oL = nullptr, *oB = nullptr, *oS = nullptr, *oP = nullptr;
    const int FULL_SZ = BSZ * NA * (1 + 4 + NC + 1);   // 23,116,800
    if (out_size == FULL_SZ) {
        oL = out;
        oB = out + BSZ * NA;
        oS = oB + BSZ * NA * 4;
        oP = oS + (size_t)BSZ * NA * NC;
    } else {
        oS = out;   // fallback: scores-only output
    }

    k_init<<<(BSZ * NA + 255) / 256, 256>>>();
    k_topk<<<(BSZ * NM + 7) / 8, 256>>>(ps, pb, ap, gl, gb, mg);
    k_assign<<<dim3((NA + 127) / 128, BSZ), 128>>>(ps, pb, gb, gl);
    k_final<<<dim3((NA + 63) / 64, BSZ), 256>>>(gb, gl, oL, oB, oS, oP);
}